// round 1
// baseline (speedup 1.0000x reference)
#include <cuda_runtime.h>
#include <math.h>

#define BATCH   8
#define NNODES  2048
#define FDIM    256
#define HEADS   4
#define DDIM    64
#define HD      256              // HEADS*DDIM
#define MTOT    (BATCH*NNODES)   // 16384

// ---- scratch (device globals: no allocation allowed in kernel_launch) ----
__device__ float g_Wh[MTOT * HD];            // 16.7 MB
__device__ float g_e[MTOT * HEADS];
__device__ float g_soft[BATCH * HEADS * NNODES];
__device__ float g_att[MTOT];

// ============================================================
// Kernel A: Wh = X @ W   ([16384,256] @ [256,256])
// fused: e[m][h] = sum over that head's 64 cols of Wh^2
// Tiling: BM=64, BN=64(=one head), BK=16, 256 threads, 4x4 microtile
// ============================================================
__global__ __launch_bounds__(256) void k_wh(const float* __restrict__ X,
                                            const float* __restrict__ W) {
    __shared__ float As[16][68];
    __shared__ float Bs[16][68];
    __shared__ float esh[64][17];

    const int t    = threadIdx.x;
    const int m0   = blockIdx.y * 64;
    const int n0   = blockIdx.x * 64;     // == head * 64
    const int trow = t >> 4;              // 0..15
    const int tcol = t & 15;              // 0..15

    float acc[4][4] = {};

    for (int k0 = 0; k0 < FDIM; k0 += 16) {
        {   // A tile: 64 rows x 16 k  (1 float4 per thread)
            int i = t >> 2;
            int q = t & 3;
            float4 v = *(const float4*)(X + (size_t)(m0 + i) * FDIM + k0 + q * 4);
            As[q*4+0][i] = v.x; As[q*4+1][i] = v.y;
            As[q*4+2][i] = v.z; As[q*4+3][i] = v.w;
        }
        {   // B tile: 16 k x 64 cols (1 float4 per thread)
            int k  = t >> 4;
            int j4 = (t & 15) << 2;
            *(float4*)&Bs[k][j4] = *(const float4*)(W + (size_t)(k0 + k) * HD + n0 + j4);
        }
        __syncthreads();
        #pragma unroll
        for (int k = 0; k < 16; k++) {
            float a[4], b[4];
            #pragma unroll
            for (int i = 0; i < 4; i++) a[i] = As[k][trow*4 + i];
            #pragma unroll
            for (int j = 0; j < 4; j++) b[j] = Bs[k][tcol*4 + j];
            #pragma unroll
            for (int i = 0; i < 4; i++)
                #pragma unroll
                for (int j = 0; j < 4; j++)
                    acc[i][j] = fmaf(a[i], b[j], acc[i][j]);
        }
        __syncthreads();
    }

    // write Wh tile + per-row partial sum-of-squares (deterministic reduce)
    #pragma unroll
    for (int i = 0; i < 4; i++) {
        int m = m0 + trow*4 + i;
        float s = acc[i][0]*acc[i][0] + acc[i][1]*acc[i][1]
                + acc[i][2]*acc[i][2] + acc[i][3]*acc[i][3];
        esh[trow*4 + i][tcol] = s;
        float4 o = make_float4(acc[i][0], acc[i][1], acc[i][2], acc[i][3]);
        *(float4*)(g_Wh + (size_t)m * HD + n0 + tcol*4) = o;
    }
    __syncthreads();
    if (t < 64) {
        float s = 0.f;
        #pragma unroll
        for (int j = 0; j < 16; j++) s += esh[t][j];
        g_e[(size_t)(m0 + t) * HEADS + (n0 >> 6)] = s;
    }
}

// ============================================================
// Kernel B1: softmax over nodes per (b,h)
// ============================================================
__global__ __launch_bounds__(256) void k_softmax() {
    const int b = blockIdx.x >> 2;
    const int h = blockIdx.x & 3;
    const int t = threadIdx.x;
    __shared__ float red[256];

    float mx = -1e30f;
    for (int n = t; n < NNODES; n += 256)
        mx = fmaxf(mx, g_e[(size_t)(b*NNODES + n) * HEADS + h]);
    red[t] = mx; __syncthreads();
    for (int s = 128; s > 0; s >>= 1) {
        if (t < s) red[t] = fmaxf(red[t], red[t + s]);
        __syncthreads();
    }
    mx = red[0]; __syncthreads();

    float sum = 0.f;
    for (int n = t; n < NNODES; n += 256)
        sum += __expf(g_e[(size_t)(b*NNODES + n) * HEADS + h] - mx);
    red[t] = sum; __syncthreads();
    for (int s = 128; s > 0; s >>= 1) {
        if (t < s) red[t] += red[t + s];
        __syncthreads();
    }
    float inv = 1.0f / red[0];

    for (int n = t; n < NNODES; n += 256)
        g_soft[(size_t)(b*HEADS + h) * NNODES + n] =
            __expf(g_e[(size_t)(b*NNODES + n) * HEADS + h] - mx) * inv;
}

// ============================================================
// Kernel B2: att[b,n] = mean over heads
// ============================================================
__global__ __launch_bounds__(256) void k_att() {
    int m = blockIdx.x * 256 + threadIdx.x;
    if (m >= MTOT) return;
    int b = m / NNODES, n = m % NNODES;
    const float* s = g_soft + (size_t)b * HEADS * NNODES + n;
    g_att[m] = 0.25f * (s[0] + s[NNODES] + s[2*NNODES] + s[3*NNODES]);
}

// ============================================================
// Kernel C: out[b,i,:] = relu(att[b,i] * (adj[b,i,:] @ Wh[b]) + bias)
// GEMM per batch: M=2048, N=256, K=2048
// Tiling: BM=128, BN=64, BK=16, 256 threads, 8x4 microtile
// ============================================================
__global__ __launch_bounds__(256) void k_out(const float* __restrict__ adj,
                                             const float* __restrict__ bias,
                                             float* __restrict__ out) {
    __shared__ float As[16][132];
    __shared__ float Bs[16][68];

    const int t  = threadIdx.x;
    const int b  = blockIdx.z;
    const int m0 = blockIdx.y * 128;
    const int n0 = blockIdx.x * 64;
    const float* adjb = adj + (size_t)b * NNODES * NNODES;
    const float* Whb  = g_Wh + (size_t)b * NNODES * HD;

    const int trow = t >> 4;   // 0..15 -> rows trow*8..+7
    const int tcol = t & 15;   // 0..15 -> cols tcol*4..+3

    float acc[8][4] = {};

    for (int k0 = 0; k0 < NNODES; k0 += 16) {
        // A tile: 128 rows x 16 k = 512 float4, 2 per thread
        #pragma unroll
        for (int it = 0; it < 2; it++) {
            int idx = t + it * 256;
            int i = idx & 127;
            int q = idx >> 7;    // 0..3
            float4 v = *(const float4*)(adjb + (size_t)(m0 + i) * NNODES + k0 + q*4);
            As[q*4+0][i] = v.x; As[q*4+1][i] = v.y;
            As[q*4+2][i] = v.z; As[q*4+3][i] = v.w;
        }
        {   // B tile: 16 k x 64 cols
            int k  = t >> 4;
            int j4 = (t & 15) << 2;
            *(float4*)&Bs[k][j4] = *(const float4*)(Whb + (size_t)(k0 + k) * HD + n0 + j4);
        }
        __syncthreads();
        #pragma unroll
        for (int k = 0; k < 16; k++) {
            float a[8], bb[4];
            #pragma unroll
            for (int i = 0; i < 8; i++) a[i] = As[k][trow*8 + i];
            #pragma unroll
            for (int j = 0; j < 4; j++) bb[j] = Bs[k][tcol*4 + j];
            #pragma unroll
            for (int i = 0; i < 8; i++)
                #pragma unroll
                for (int j = 0; j < 4; j++)
                    acc[i][j] = fmaf(a[i], bb[j], acc[i][j]);
        }
        __syncthreads();
    }

    float bv[4];
    #pragma unroll
    for (int j = 0; j < 4; j++) bv[j] = bias[n0 + tcol*4 + j];

    #pragma unroll
    for (int i = 0; i < 8; i++) {
        int m = m0 + trow*8 + i;
        float att = g_att[b * NNODES + m];
        float4 o;
        o.x = fmaxf(fmaf(att, acc[i][0], bv[0]), 0.f);
        o.y = fmaxf(fmaf(att, acc[i][1], bv[1]), 0.f);
        o.z = fmaxf(fmaf(att, acc[i][2], bv[2]), 0.f);
        o.w = fmaxf(fmaf(att, acc[i][3], bv[3]), 0.f);
        *(float4*)(out + ((size_t)(b * NNODES + m)) * HD + n0 + tcol*4) = o;
    }
}

// ============================================================
extern "C" void kernel_launch(void* const* d_in, const int* in_sizes, int n_in,
                              void* d_out, int out_size) {
    const float* features = (const float*)d_in[0];   // [8,2048,256]
    const float* adj      = (const float*)d_in[1];   // [8,2048,2048]
    const float* W        = (const float*)d_in[2];   // [256,256]
    const float* bias     = (const float*)d_in[3];   // [256]
    float* out = (float*)d_out;                      // [8,2048,256]

    k_wh     <<<dim3(HD/64, MTOT/64), 256>>>(features, W);
    k_softmax<<<BATCH*HEADS, 256>>>();
    k_att    <<<MTOT/256, 256>>>();
    k_out    <<<dim3(HD/64, NNODES/128, BATCH), 256>>>(adj, bias, out);
}

// round 3
// speedup vs baseline: 2.3405x; 2.3405x over previous
#include <cuda_runtime.h>
#include <cuda_bf16.h>
#include <cstdint>
#include <math.h>

#define BATCH   8
#define NNODES  2048
#define FDIM    256
#define HEADS   4
#define HD      256
#define MTOT    (BATCH*NNODES)

// ---- scratch ----
__device__ __nv_bfloat16 g_WhT_hi[(size_t)BATCH * HD * NNODES];  // Wh^T, bf16 hi part
__device__ __nv_bfloat16 g_WhT_lo[(size_t)BATCH * HD * NNODES];  // residual part
__device__ float g_e[MTOT * HEADS];
__device__ float g_soft[BATCH * HEADS * NNODES];
__device__ float g_att[MTOT];

// ================= helpers =================
__device__ __forceinline__ uint32_t smem_u32(const void* p) {
    uint32_t a;
    asm("{ .reg .u64 t; cvta.to.shared.u64 t, %1; cvt.u32.u64 %0, t; }" : "=r"(a) : "l"(p));
    return a;
}
// pack two floats into bf16x2 (hi) and residual bf16x2 (lo)
__device__ __forceinline__ void split2(float x, float y, uint32_t& hi, uint32_t& lo) {
    __nv_bfloat16 hx = __float2bfloat16_rn(x);
    __nv_bfloat16 hy = __float2bfloat16_rn(y);
    __nv_bfloat16 lx = __float2bfloat16_rn(x - __bfloat162float(hx));
    __nv_bfloat16 ly = __float2bfloat16_rn(y - __bfloat162float(hy));
    __nv_bfloat162 H; H.x = hx; H.y = hy;
    __nv_bfloat162 L; L.x = lx; L.y = ly;
    hi = *(uint32_t*)&H;
    lo = *(uint32_t*)&L;
}
// swizzled byte offset within a 128-row x 64B tile (rows of 4x16B units)
__device__ __forceinline__ uint32_t swa(int row, int u) {
    return (uint32_t)(row * 64 + (((u ^ ((row >> 1) & 3))) << 4));
}
__device__ __forceinline__ uint32_t fragaddr(uint32_t base, int row_base, int lane, int u0) {
    int r = row_base + (lane & 15);
    int u = u0 + (lane >> 4);
    return base + swa(r, u);
}

#define LDSM4(r, a) \
    asm volatile("ldmatrix.sync.aligned.m8n8.x4.shared.b16 {%0,%1,%2,%3}, [%4];" \
        : "=r"((r)[0]), "=r"((r)[1]), "=r"((r)[2]), "=r"((r)[3]) : "r"(a))

#define MMA16816(c, a, b0, b1) \
    asm volatile("mma.sync.aligned.m16n8k16.row.col.f32.bf16.bf16.f32 " \
        "{%0,%1,%2,%3}, {%4,%5,%6,%7}, {%8,%9}, {%0,%1,%2,%3};" \
        : "+f"((c)[0]), "+f"((c)[1]), "+f"((c)[2]), "+f"((c)[3]) \
        : "r"((a)[0]), "r"((a)[1]), "r"((a)[2]), "r"((a)[3]), "r"(b0), "r"(b1))

#define CPASYNC16(dst, src) \
    asm volatile("cp.async.ca.shared.global [%0], [%1], 16;" :: "r"(dst), "l"(src))
#define CPCOMMIT() asm volatile("cp.async.commit_group;")
#define CPWAIT0()  asm volatile("cp.async.wait_group 0;")

// ============================================================
// Kernel A: Wh = X @ W; writes WhT split to bf16 hi/lo; e = ||Wh_head||^2 per row
// ============================================================
__global__ __launch_bounds__(256) void k_wh(const float* __restrict__ X,
                                            const float* __restrict__ W) {
    __shared__ float As[16][68];
    __shared__ float Bs[16][68];
    __shared__ float esh[64][17];

    const int t    = threadIdx.x;
    const int m0   = blockIdx.y * 64;
    const int n0   = blockIdx.x * 64;
    const int trow = t >> 4;
    const int tcol = t & 15;

    float acc[4][4] = {};

    for (int k0 = 0; k0 < FDIM; k0 += 16) {
        {
            int i = t >> 2, q = t & 3;
            float4 v = *(const float4*)(X + (size_t)(m0 + i) * FDIM + k0 + q * 4);
            As[q*4+0][i] = v.x; As[q*4+1][i] = v.y;
            As[q*4+2][i] = v.z; As[q*4+3][i] = v.w;
        }
        {
            int k = t >> 4, j4 = (t & 15) << 2;
            *(float4*)&Bs[k][j4] = *(const float4*)(W + (size_t)(k0 + k) * HD + n0 + j4);
        }
        __syncthreads();
        #pragma unroll
        for (int k = 0; k < 16; k++) {
            float a[4], b[4];
            #pragma unroll
            for (int i = 0; i < 4; i++) a[i] = As[k][trow*4 + i];
            #pragma unroll
            for (int j = 0; j < 4; j++) b[j] = Bs[k][tcol*4 + j];
            #pragma unroll
            for (int i = 0; i < 4; i++)
                #pragma unroll
                for (int j = 0; j < 4; j++)
                    acc[i][j] = fmaf(a[i], b[j], acc[i][j]);
        }
        __syncthreads();
    }

    const int b     = m0 >> 11;
    const int node0 = (m0 & 2047) + trow * 4;

    // transposed bf16-split write: WhT[(b*256 + feat)][node]
    #pragma unroll
    for (int j = 0; j < 4; j++) {
        int feat = n0 + tcol * 4 + j;
        size_t base = ((size_t)(b * HD + feat)) * NNODES + node0;
        uint32_t h01, l01, h23, l23;
        split2(acc[0][j], acc[1][j], h01, l01);
        split2(acc[2][j], acc[3][j], h23, l23);
        *(uint32_t*)(g_WhT_hi + base)     = h01;
        *(uint32_t*)(g_WhT_hi + base + 2) = h23;
        *(uint32_t*)(g_WhT_lo + base)     = l01;
        *(uint32_t*)(g_WhT_lo + base + 2) = l23;
    }

    #pragma unroll
    for (int i = 0; i < 4; i++) {
        float s = acc[i][0]*acc[i][0] + acc[i][1]*acc[i][1]
                + acc[i][2]*acc[i][2] + acc[i][3]*acc[i][3];
        esh[trow*4 + i][tcol] = s;
    }
    __syncthreads();
    if (t < 64) {
        float s = 0.f;
        #pragma unroll
        for (int j = 0; j < 16; j++) s += esh[t][j];
        g_e[(size_t)(m0 + t) * HEADS + (n0 >> 6)] = s;
    }
}

// ============================================================
// Kernel B1: softmax over nodes per (b,h)
// ============================================================
__global__ __launch_bounds__(256) void k_softmax() {
    const int b = blockIdx.x >> 2;
    const int h = blockIdx.x & 3;
    const int t = threadIdx.x;
    __shared__ float red[256];

    float mx = -1e30f;
    for (int n = t; n < NNODES; n += 256)
        mx = fmaxf(mx, g_e[(size_t)(b*NNODES + n) * HEADS + h]);
    red[t] = mx; __syncthreads();
    for (int s = 128; s > 0; s >>= 1) {
        if (t < s) red[t] = fmaxf(red[t], red[t + s]);
        __syncthreads();
    }
    mx = red[0]; __syncthreads();

    float sum = 0.f;
    for (int n = t; n < NNODES; n += 256)
        sum += __expf(g_e[(size_t)(b*NNODES + n) * HEADS + h] - mx);
    red[t] = sum; __syncthreads();
    for (int s = 128; s > 0; s >>= 1) {
        if (t < s) red[t] += red[t + s];
        __syncthreads();
    }
    float inv = 1.0f / red[0];

    for (int n = t; n < NNODES; n += 256)
        g_soft[(size_t)(b*HEADS + h) * NNODES + n] =
            __expf(g_e[(size_t)(b*NNODES + n) * HEADS + h] - mx) * inv;
}

// ============================================================
// Kernel B2: att = head mean
// ============================================================
__global__ __launch_bounds__(256) void k_att() {
    int m = blockIdx.x * 256 + threadIdx.x;
    if (m >= MTOT) return;
    int b = m / NNODES, n = m % NNODES;
    const float* s = g_soft + (size_t)b * HEADS * NNODES + n;
    g_att[m] = 0.25f * (s[0] + s[NNODES] + s[2*NNODES] + s[3*NNODES]);
}

// ============================================================
// Kernel C: mma.sync bf16x3 GEMM: out = relu(att*(adj @ Wh) + bias)
// BM=128, BN=128, BK=32, 8 warps (4m x 2n), double-buffered SMEM
// ============================================================
#define A_HI  0
#define A_LO  8192
#define B_HI  16384
#define B_LO  24576
#define STAGE 32768

__global__ void __launch_bounds__(256, 1)
k_out_mma(const float* __restrict__ adj, const float* __restrict__ bias,
          float* __restrict__ out) {
    extern __shared__ char smem[];
    const uint32_t sb = smem_u32(smem);
    const int t    = threadIdx.x;
    const int lane = t & 31;
    const int wid  = t >> 5;
    const int b    = blockIdx.z;
    const int m0   = blockIdx.x * 128;
    const int n0   = blockIdx.y * 128;
    const int warp_m = wid & 3;   // 32 rows each
    const int warp_n = wid >> 2;  // 64 cols each

    const float* adjb = adj + (size_t)b * NNODES * NNODES;
    const __nv_bfloat16* BhG = g_WhT_hi + ((size_t)(b * HD + n0)) * NNODES;
    const __nv_bfloat16* BlG = g_WhT_lo + ((size_t)(b * HD + n0)) * NNODES;

    float c[2][8][4];
    #pragma unroll
    for (int mt = 0; mt < 2; mt++)
        #pragma unroll
        for (int nt = 0; nt < 8; nt++)
            #pragma unroll
            for (int j = 0; j < 4; j++) c[mt][nt][j] = 0.f;

    float4 pa[2][2];

    // ---- prologue: tile 0 ----
    #pragma unroll
    for (int it = 0; it < 2; it++) {
        int idx = t + it * 256, row = idx >> 2, cc = idx & 3;
        const float* p = adjb + (size_t)(m0 + row) * NNODES + cc * 8;
        pa[it][0] = *(const float4*)p;
        pa[it][1] = *(const float4*)(p + 4);
    }
    #pragma unroll
    for (int it = 0; it < 2; it++) {
        int idx = t + it * 256, row = idx >> 2, u = idx & 3;
        size_t g = (size_t)row * NNODES + u * 8;
        CPASYNC16(sb + B_HI + swa(row, u), BhG + g);
        CPASYNC16(sb + B_LO + swa(row, u), BlG + g);
    }
    CPCOMMIT();
    #pragma unroll
    for (int it = 0; it < 2; it++) {
        int idx = t + it * 256, row = idx >> 2, cc = idx & 3;
        float f[8] = {pa[it][0].x, pa[it][0].y, pa[it][0].z, pa[it][0].w,
                      pa[it][1].x, pa[it][1].y, pa[it][1].z, pa[it][1].w};
        uint32_t hi[4], lo[4];
        #pragma unroll
        for (int j = 0; j < 4; j++) split2(f[2*j], f[2*j+1], hi[j], lo[j]);
        uint32_t off = swa(row, cc);
        *(uint4*)(smem + A_HI + off) = make_uint4(hi[0], hi[1], hi[2], hi[3]);
        *(uint4*)(smem + A_LO + off) = make_uint4(lo[0], lo[1], lo[2], lo[3]);
    }
    CPWAIT0();
    __syncthreads();

    // ---- main loop ----
    for (int i = 0; i < 64; i++) {
        const uint32_t cur = sb + (uint32_t)(i & 1) * STAGE;

        if (i < 63) {
            const int k0 = (i + 1) * 32;
            #pragma unroll
            for (int it = 0; it < 2; it++) {
                int idx = t + it * 256, row = idx >> 2, cc = idx & 3;
                const float* p = adjb + (size_t)(m0 + row) * NNODES + k0 + cc * 8;
                pa[it][0] = *(const float4*)p;
                pa[it][1] = *(const float4*)(p + 4);
            }
            const uint32_t nxt = sb + (uint32_t)((i + 1) & 1) * STAGE;
            #pragma unroll
            for (int it = 0; it < 2; it++) {
                int idx = t + it * 256, row = idx >> 2, u = idx & 3;
                size_t g = (size_t)row * NNODES + k0 + u * 8;
                CPASYNC16(nxt + B_HI + swa(row, u), BhG + g);
                CPASYNC16(nxt + B_LO + swa(row, u), BlG + g);
            }
            CPCOMMIT();
        }

        // compute on current stage
        #pragma unroll
        for (int kk = 0; kk < 2; kk++) {
            uint32_t ahi[2][4], alo[2][4];
            #pragma unroll
            for (int mt = 0; mt < 2; mt++) {
                LDSM4(ahi[mt], fragaddr(cur + A_HI, warp_m*32 + mt*16, lane, kk*2));
                LDSM4(alo[mt], fragaddr(cur + A_LO, warp_m*32 + mt*16, lane, kk*2));
            }
            #pragma unroll
            for (int ng = 0; ng < 4; ng++) {
                uint32_t bhi[4], blo[4];
                LDSM4(bhi, fragaddr(cur + B_HI, warp_n*64 + ng*16, lane, kk*2));
                LDSM4(blo, fragaddr(cur + B_LO, warp_n*64 + ng*16, lane, kk*2));
                #pragma unroll
                for (int mt = 0; mt < 2; mt++) {
                    MMA16816(c[mt][2*ng],   ahi[mt], bhi[0], bhi[2]);
                    MMA16816(c[mt][2*ng],   ahi[mt], blo[0], blo[2]);
                    MMA16816(c[mt][2*ng],   alo[mt], bhi[0], bhi[2]);
                    MMA16816(c[mt][2*ng+1], ahi[mt], bhi[1], bhi[3]);
                    MMA16816(c[mt][2*ng+1], ahi[mt], blo[1], blo[3]);
                    MMA16816(c[mt][2*ng+1], alo[mt], bhi[1], bhi[3]);
                }
            }
        }

        if (i < 63) {
            char* nsp = smem + ((i + 1) & 1) * STAGE;
            #pragma unroll
            for (int it = 0; it < 2; it++) {
                int idx = t + it * 256, row = idx >> 2, cc = idx & 3;
                float f[8] = {pa[it][0].x, pa[it][0].y, pa[it][0].z, pa[it][0].w,
                              pa[it][1].x, pa[it][1].y, pa[it][1].z, pa[it][1].w};
                uint32_t hi[4], lo[4];
                #pragma unroll
                for (int j = 0; j < 4; j++) split2(f[2*j], f[2*j+1], hi[j], lo[j]);
                uint32_t off = swa(row, cc);
                *(uint4*)(nsp + A_HI + off) = make_uint4(hi[0], hi[1], hi[2], hi[3]);
                *(uint4*)(nsp + A_LO + off) = make_uint4(lo[0], lo[1], lo[2], lo[3]);
            }
            CPWAIT0();
            __syncthreads();
        }
    }

    // ---- epilogue ----
    #pragma unroll
    for (int mt = 0; mt < 2; mt++) {
        int r0 = m0 + warp_m * 32 + mt * 16 + (lane >> 2);
        float att0 = g_att[b * NNODES + r0];
        float att1 = g_att[b * NNODES + r0 + 8];
        float* o0 = out + ((size_t)(b * NNODES + r0)) * HD;
        float* o1 = o0 + (size_t)8 * HD;
        #pragma unroll
        for (int nt = 0; nt < 8; nt++) {
            int col = n0 + warp_n * 64 + nt * 8 + 2 * (lane & 3);
            float2 bv = *(const float2*)(bias + col);
            float2 v0, v1;
            v0.x = fmaxf(fmaf(att0, c[mt][nt][0], bv.x), 0.f);
            v0.y = fmaxf(fmaf(att0, c[mt][nt][1], bv.y), 0.f);
            v1.x = fmaxf(fmaf(att1, c[mt][nt][2], bv.x), 0.f);
            v1.y = fmaxf(fmaf(att1, c[mt][nt][3], bv.y), 0.f);
            *(float2*)(o0 + col) = v0;
            *(float2*)(o1 + col) = v1;
        }
    }
}

// ============================================================
extern "C" void kernel_launch(void* const* d_in, const int* in_sizes, int n_in,
                              void* d_out, int out_size) {
    const float* features = (const float*)d_in[0];   // [8,2048,256]
    const float* adj      = (const float*)d_in[1];   // [8,2048,2048]
    const float* W        = (const float*)d_in[2];   // [256,256]
    const float* bias     = (const float*)d_in[3];   // [256]
    float* out = (float*)d_out;                      // [8,2048,256]

    cudaFuncSetAttribute(k_out_mma, cudaFuncAttributeMaxDynamicSharedMemorySize, 2 * STAGE);

    k_wh     <<<dim3(HD/64, MTOT/64), 256>>>(features, W);
    k_softmax<<<BATCH*HEADS, 256>>>();
    k_att    <<<MTOT/256, 256>>>();
    k_out_mma<<<dim3(NNODES/128, HD/128, BATCH), 256, 2 * STAGE>>>(adj, bias, out);
}